// round 17
// baseline (speedup 1.0000x reference)
#include <cuda_runtime.h>
#include <cuda_bf16.h>
#include <math.h>
#include <stdint.h>

// Problem constants
#define BB   2
#define SS   2048
#define HIDD 2048
#define NH   32
#define NKV  8
#define HD   64
#define NREP 4

// ---------------------------------------------------------------------------
// Device-global scratch (allocation-free rule)
// ---------------------------------------------------------------------------
__device__ float g_q[BB * SS * NH * HD];     // fp32 pre-RoPE
__device__ float g_k[BB * SS * NKV * HD];
__device__ float g_v[BB * SS * NKV * HD];

__device__ __nv_bfloat16 g_x_hi[BB * SS * HIDD];
__device__ __nv_bfloat16 g_x_lo[BB * SS * HIDD];
__device__ __nv_bfloat16 g_wq_hi[NH * HD * HIDD];
__device__ __nv_bfloat16 g_wq_lo[NH * HD * HIDD];
__device__ __nv_bfloat16 g_wk_hi[NKV * HD * HIDD];
__device__ __nv_bfloat16 g_wk_lo[NKV * HD * HIDD];
__device__ __nv_bfloat16 g_wv_hi[NKV * HD * HIDD];
__device__ __nv_bfloat16 g_wv_lo[NKV * HD * HIDD];
__device__ __nv_bfloat16 g_wo_hi[HIDD * NH * HD];
__device__ __nv_bfloat16 g_wo_lo[HIDD * NH * HD];
__device__ __nv_bfloat16 g_a_hi[BB * SS * NH * HD];
__device__ __nv_bfloat16 g_a_lo[BB * SS * NH * HD];

__device__ __nv_bfloat16 g_qh[BB * SS * NH * HD];
__device__ __nv_bfloat16 g_ql[BB * SS * NH * HD];
__device__ __nv_bfloat16 g_kh[BB * SS * NKV * HD];
__device__ __nv_bfloat16 g_kl[BB * SS * NKV * HD];
__device__ __nv_bfloat16 g_vh[BB * SS * NKV * HD];
__device__ __nv_bfloat16 g_vl[BB * SS * NKV * HD];

// ---------------------------------------------------------------------------
// Helpers
// ---------------------------------------------------------------------------
__device__ __forceinline__ uint32_t smem_u32(const void* p) {
    uint32_t a;
    asm("{ .reg .u64 t; cvta.to.shared.u64 t, %1; cvt.u32.u64 %0, t; }"
        : "=r"(a) : "l"(p));
    return a;
}

// Tiles with 128B rows, 8 x 16B chunks: conflict-free for STS.128/cp.async,
// ldmatrix and ldmatrix.trans.
__device__ __forceinline__ uint32_t sw_off8(int row, int ch) {
    return (uint32_t)(row * 128 + ((ch ^ (row & 7)) << 4));
}

__device__ __forceinline__ void ldsm_x4(uint32_t addr, uint32_t& r0, uint32_t& r1,
                                        uint32_t& r2, uint32_t& r3) {
    asm volatile("ldmatrix.sync.aligned.m8n8.x4.shared.b16 {%0,%1,%2,%3}, [%4];"
                 : "=r"(r0), "=r"(r1), "=r"(r2), "=r"(r3) : "r"(addr));
}
__device__ __forceinline__ void ldsm_x4_t(uint32_t addr, uint32_t& r0, uint32_t& r1,
                                          uint32_t& r2, uint32_t& r3) {
    asm volatile("ldmatrix.sync.aligned.m8n8.x4.trans.shared.b16 {%0,%1,%2,%3}, [%4];"
                 : "=r"(r0), "=r"(r1), "=r"(r2), "=r"(r3) : "r"(addr));
}

__device__ __forceinline__ void mma_bf16(float* c, const uint32_t* a, const uint32_t* b) {
    asm volatile(
        "mma.sync.aligned.m16n8k16.row.col.f32.bf16.bf16.f32 "
        "{%0,%1,%2,%3}, {%4,%5,%6,%7}, {%8,%9}, {%0,%1,%2,%3};"
        : "+f"(c[0]), "+f"(c[1]), "+f"(c[2]), "+f"(c[3])
        : "r"(a[0]), "r"(a[1]), "r"(a[2]), "r"(a[3]), "r"(b[0]), "r"(b[1]));
}

__device__ __forceinline__ uint32_t pack_bf16(float a, float b) {
    __nv_bfloat162 t = __floats2bfloat162_rn(a, b);
    return *(uint32_t*)&t;
}

__device__ __forceinline__ void cp_async16(uint32_t saddr, const void* g) {
    asm volatile("cp.async.cg.shared.global [%0], [%1], 16;" :: "r"(saddr), "l"(g));
}
#define CP_COMMIT() asm volatile("cp.async.commit_group;")
#define CP_WAIT(n)  asm volatile("cp.async.wait_group %0;" :: "n"(n))

// ---------------------------------------------------------------------------
// Split fp32 -> (hi, lo) bf16
// ---------------------------------------------------------------------------
__global__ void cvt_split(const float* __restrict__ in,
                          __nv_bfloat16* __restrict__ hi,
                          __nv_bfloat16* __restrict__ lo, int n) {
    int i = (blockIdx.x * blockDim.x + threadIdx.x) * 4;
    if (i >= n) return;
    float4 f = *(const float4*)(in + i);
    __nv_bfloat16 h0 = __float2bfloat16(f.x);
    __nv_bfloat16 h1 = __float2bfloat16(f.y);
    __nv_bfloat16 h2 = __float2bfloat16(f.z);
    __nv_bfloat16 h3 = __float2bfloat16(f.w);
    __nv_bfloat16 l0 = __float2bfloat16(f.x - __bfloat162float(h0));
    __nv_bfloat16 l1 = __float2bfloat16(f.y - __bfloat162float(h1));
    __nv_bfloat16 l2 = __float2bfloat16(f.z - __bfloat162float(h2));
    __nv_bfloat16 l3 = __float2bfloat16(f.w - __bfloat162float(h3));
    __nv_bfloat162* hp = (__nv_bfloat162*)(hi + i);
    __nv_bfloat162* lp = (__nv_bfloat162*)(lo + i);
    hp[0] = __nv_bfloat162(h0, h1);
    hp[1] = __nv_bfloat162(h2, h3);
    lp[0] = __nv_bfloat162(l0, l1);
    lp[1] = __nv_bfloat162(l2, l3);
}

// ---------------------------------------------------------------------------
// Pipelined split-bf16 GEMM body, BK=64, 512 threads (16 warps, 4x4 grid,
// warp-tile 32x32). Low register footprint (~100) -> 4 warps/SMSP for
// latency hiding. Stage (64KB): Ah@0 Al@16384 Bh@32768 Bl@49152; 2 stages.
// ---------------------------------------------------------------------------
__device__ __forceinline__ void gemm_body(
    const char* __restrict__ aH, const char* __restrict__ aL,
    const char* __restrict__ bH, const char* __restrict__ bL,
    float* __restrict__ C, int ldc, int K, char* sm) {
    const int tid = threadIdx.x;            // 0..511
    const int wid = tid >> 5;               // 0..15
    const int lid = tid & 31;
    const int m0w = (wid >> 2) * 32;
    const int n0w = (wid & 3) * 32;
    const long ldb = (long)K * 2;

    // 2 x 16B chunks per thread per array (128 rows x 128B tile, 1024 chunks)
    uint32_t so[2];
    long go[2];
#pragma unroll
    for (int i = 0; i < 2; i++) {
        int c = tid + i * 512;
        int row = c >> 3, ch = c & 7;
        so[i] = sw_off8(row, ch);
        go[i] = (long)row * ldb + ch * 16;
    }

    const uint32_t uS = smem_u32(sm);

    float acc[2][4][4];
#pragma unroll
    for (int i = 0; i < 2; i++)
#pragma unroll
        for (int j = 0; j < 4; j++)
#pragma unroll
            for (int v = 0; v < 4; v++) acc[i][j][v] = 0.f;

    const int niter = K >> 6;

    // issue stage 0
#pragma unroll
    for (int i = 0; i < 2; i++) {
        cp_async16(uS + so[i], aH + go[i]);
        cp_async16(uS + 16384 + so[i], aL + go[i]);
        cp_async16(uS + 32768 + so[i], bH + go[i]);
        cp_async16(uS + 49152 + so[i], bL + go[i]);
    }
    CP_COMMIT();

    for (int it = 0; it < niter; it++) {
        if (it + 1 < niter) {
            const uint32_t sb = uS + ((it + 1) & 1) * 65536;
            const long kb = (long)(it + 1) * 128;
#pragma unroll
            for (int i = 0; i < 2; i++) {
                cp_async16(sb + so[i], aH + go[i] + kb);
                cp_async16(sb + 16384 + so[i], aL + go[i] + kb);
                cp_async16(sb + 32768 + so[i], bH + go[i] + kb);
                cp_async16(sb + 49152 + so[i], bL + go[i] + kb);
            }
            CP_COMMIT();
            CP_WAIT(1);
        } else {
            CP_WAIT(0);
        }
        __syncthreads();

        const uint32_t uAh = uS + (it & 1) * 65536;
        const uint32_t uAl = uAh + 16384;
        const uint32_t uBh = uAh + 32768;
        const uint32_t uBl = uAh + 49152;

#pragma unroll
        for (int ks = 0; ks < 4; ks++) {
            uint32_t ah[2][4], al[2][4], bh[4][2], bl[4][2];
            const int arow = m0w + (lid & 15);
            const int ach = ks * 2 + (lid >> 4);
#pragma unroll
            for (int mi = 0; mi < 2; mi++) {
                uint32_t off = sw_off8(arow + mi * 16, ach);
                ldsm_x4(uAh + off, ah[mi][0], ah[mi][1], ah[mi][2], ah[mi][3]);
                ldsm_x4(uAl + off, al[mi][0], al[mi][1], al[mi][2], al[mi][3]);
            }
            const int brow = n0w + (lid & 15);
#pragma unroll
            for (int g = 0; g < 2; g++) {
                uint32_t off = sw_off8(brow + g * 16, ach);
                uint32_t t0, t1, t2, t3;
                ldsm_x4(uBh + off, t0, t1, t2, t3);
                bh[2 * g][0] = t0; bh[2 * g][1] = t2;
                bh[2 * g + 1][0] = t1; bh[2 * g + 1][1] = t3;
                ldsm_x4(uBl + off, t0, t1, t2, t3);
                bl[2 * g][0] = t0; bl[2 * g][1] = t2;
                bl[2 * g + 1][0] = t1; bl[2 * g + 1][1] = t3;
            }
            // Phase 1: hi*hi (8 independent accumulators)
#pragma unroll
            for (int mi = 0; mi < 2; mi++)
#pragma unroll
                for (int nj = 0; nj < 4; nj++)
                    mma_bf16(acc[mi][nj], ah[mi], bh[nj]);
            // Phase 2: hi*lo
#pragma unroll
            for (int mi = 0; mi < 2; mi++)
#pragma unroll
                for (int nj = 0; nj < 4; nj++)
                    mma_bf16(acc[mi][nj], ah[mi], bl[nj]);
            // Phase 3: lo*hi
#pragma unroll
            for (int mi = 0; mi < 2; mi++)
#pragma unroll
                for (int nj = 0; nj < 4; nj++)
                    mma_bf16(acc[mi][nj], al[mi], bh[nj]);
        }
        __syncthreads();
    }

#pragma unroll
    for (int mi = 0; mi < 2; mi++) {
#pragma unroll
        for (int nj = 0; nj < 4; nj++) {
            int row = m0w + mi * 16 + (lid >> 2);
            int col = n0w + nj * 8 + (lid & 3) * 2;
            *(float2*)&C[(long)row * ldc + col] = make_float2(acc[mi][nj][0], acc[mi][nj][1]);
            *(float2*)&C[(long)(row + 8) * ldc + col] = make_float2(acc[mi][nj][2], acc[mi][nj][3]);
        }
    }
}

// ---------------------------------------------------------------------------
// Fused Q/K/V projection GEMM. grid = (24, M/128), 512 threads.
// ---------------------------------------------------------------------------
__global__ void __launch_bounds__(512, 1)
gemm_qkv(const __nv_bfloat16* __restrict__ Xh, const __nv_bfloat16* __restrict__ Xl,
         const __nv_bfloat16* __restrict__ Wqh, const __nv_bfloat16* __restrict__ Wql,
         const __nv_bfloat16* __restrict__ Wkh, const __nv_bfloat16* __restrict__ Wkl,
         const __nv_bfloat16* __restrict__ Wvh, const __nv_bfloat16* __restrict__ Wvl,
         float* __restrict__ Q, float* __restrict__ K, float* __restrict__ V) {
    extern __shared__ __align__(16) char sm[];
    const int bx = blockIdx.x;
    const int m0 = blockIdx.y * 128;
    const int KK = HIDD;

    const __nv_bfloat16 *bh, *bl;
    float* C;
    int ldc, n0;
    if (bx < 16)      { bh = Wqh; bl = Wql; C = Q; ldc = NH * HD;  n0 = bx * 128; }
    else if (bx < 20) { bh = Wkh; bl = Wkl; C = K; ldc = NKV * HD; n0 = (bx - 16) * 128; }
    else              { bh = Wvh; bl = Wvl; C = V; ldc = NKV * HD; n0 = (bx - 20) * 128; }

    gemm_body((const char*)(Xh + (long)m0 * KK), (const char*)(Xl + (long)m0 * KK),
              (const char*)(bh + (long)n0 * KK), (const char*)(bl + (long)n0 * KK),
              C + (long)m0 * ldc + n0, ldc, KK, sm);
}

// ---------------------------------------------------------------------------
// Generic NT GEMM (output projection). grid = (N/128, M/128), 512 threads.
// ---------------------------------------------------------------------------
__global__ void __launch_bounds__(512, 1)
gemm_tc(const __nv_bfloat16* __restrict__ Ahi, const __nv_bfloat16* __restrict__ Alo,
        const __nv_bfloat16* __restrict__ Bhi, const __nv_bfloat16* __restrict__ Blo,
        float* __restrict__ C, int M, int N, int K) {
    extern __shared__ __align__(16) char sm[];
    const int m0 = blockIdx.y * 128;
    const int n0 = blockIdx.x * 128;
    gemm_body((const char*)(Ahi + (long)m0 * K), (const char*)(Alo + (long)m0 * K),
              (const char*)(Bhi + (long)n0 * K), (const char*)(Blo + (long)n0 * K),
              C + (long)m0 * N + n0, N, K, sm);
}

// ---------------------------------------------------------------------------
// RoPE + split
// ---------------------------------------------------------------------------
__global__ void rope_split(const float* __restrict__ x,
                           const float* __restrict__ cosb,
                           const float* __restrict__ sinb,
                           __nv_bfloat16* __restrict__ hi,
                           __nv_bfloat16* __restrict__ lo,
                           int nheads, int total_pairs) {
    int idx = blockIdx.x * blockDim.x + threadIdx.x;
    if (idx >= total_pairs) return;
    int i = idx & 31;
    int h = (idx >> 5) % nheads;
    int s = (idx / (32 * nheads)) % SS;
    int b = idx / (32 * nheads * SS);
    long base = ((long)(b * SS + s) * nheads + h) * HD;
    float x1 = x[base + i];
    float x2 = x[base + i + 32];
    float c1 = cosb[s * HD + i];
    float s1 = sinb[s * HD + i];
    float c2 = cosb[s * HD + i + 32];
    float s2 = sinb[s * HD + i + 32];
    float y1 = x1 * c1 - x2 * s1;
    float y2 = x2 * c2 + x1 * s2;
    __nv_bfloat16 h1 = __float2bfloat16(y1);
    __nv_bfloat16 h2 = __float2bfloat16(y2);
    hi[base + i]      = h1;
    hi[base + i + 32] = h2;
    lo[base + i]      = __float2bfloat16(y1 - __bfloat162float(h1));
    lo[base + i + 32] = __float2bfloat16(y2 - __bfloat162float(h2));
}

// ---------------------------------------------------------------------------
// Flash attention on HMMA, split-bf16, cp.async double-buffered K/V.
// (verified R15; unchanged)
// ---------------------------------------------------------------------------
__global__ void __launch_bounds__(256, 1)
flash_attn_tc(const __nv_bfloat16* __restrict__ Qh, const __nv_bfloat16* __restrict__ Ql,
              const __nv_bfloat16* __restrict__ Kh, const __nv_bfloat16* __restrict__ Kl,
              const __nv_bfloat16* __restrict__ Vh, const __nv_bfloat16* __restrict__ Vl,
              __nv_bfloat16* __restrict__ Oh, __nv_bfloat16* __restrict__ Ol) {
    extern __shared__ __align__(16) char sm[];
    const int tid = threadIdx.x;
    const int wid = tid >> 5;
    const int lid = tid & 31;
    const int h = blockIdx.y;
    const int b = blockIdx.z;
    const int s0 = blockIdx.x * 128;
    const int kvh = h >> 2;
    const float scale = 0.125f;

    const uint32_t uS = smem_u32(sm);

    {
        const char* gqh = (const char*)(Qh + (((long)(b * SS + s0)) * NH + h) * HD);
        const char* gql = (const char*)(Ql + (((long)(b * SS + s0)) * NH + h) * HD);
        const long qstr = (long)NH * HD * 2;
#pragma unroll
        for (int i = 0; i < 4; i++) {
            int c = tid + i * 256;
            int row = c >> 3, ch = c & 7;
            uint32_t so = sw_off8(row, ch);
            *(uint4*)(sm + so)         = *(const uint4*)(gqh + (long)row * qstr + ch * 16);
            *(uint4*)(sm + 16384 + so) = *(const uint4*)(gql + (long)row * qstr + ch * 16);
        }
    }
    __syncthreads();

    uint32_t qhf[4][4], qlf[4][4];
    {
        const int arow = wid * 16 + (lid & 15);
#pragma unroll
        for (int ks = 0; ks < 4; ks++) {
            int ch = 2 * ks + (lid >> 4);
            uint32_t off = sw_off8(arow, ch);
            ldsm_x4(uS + off, qhf[ks][0], qhf[ks][1], qhf[ks][2], qhf[ks][3]);
            ldsm_x4(uS + 16384 + off, qlf[ks][0], qlf[ks][1], qlf[ks][2], qlf[ks][3]);
        }
    }
    __syncthreads();

    float o[8][4];
#pragma unroll
    for (int j = 0; j < 8; j++)
#pragma unroll
        for (int v = 0; v < 4; v++) o[j][v] = 0.f;
    float m0 = -INFINITY, m1 = -INFINITY, l0 = 0.f, l1 = 0.f;

    const char* gkh = (const char*)(Kh + (((long)(b * SS)) * NKV + kvh) * HD);
    const char* gkl = (const char*)(Kl + (((long)(b * SS)) * NKV + kvh) * HD);
    const char* gvh = (const char*)(Vh + (((long)(b * SS)) * NKV + kvh) * HD);
    const char* gvl = (const char*)(Vl + (((long)(b * SS)) * NKV + kvh) * HD);
    const long kvstr = (long)NKV * HD * 2;

    uint32_t kso[2];
    long kgo_row[2];
    int kch[2];
#pragma unroll
    for (int i = 0; i < 2; i++) {
        int c = tid + i * 256;
        int row = c >> 3, ch = c & 7;
        kso[i] = sw_off8(row, ch);
        kgo_row[i] = row;
        kch[i] = ch;
    }

#pragma unroll
    for (int i = 0; i < 2; i++) {
        long go = kgo_row[i] * kvstr + kch[i] * 16;
        cp_async16(uS + kso[i], gkh + go);
        cp_async16(uS + 8192 + kso[i], gkl + go);
        cp_async16(uS + 16384 + kso[i], gvh + go);
        cp_async16(uS + 24576 + kso[i], gvl + go);
    }
    CP_COMMIT();

    const int ntiles = SS / 64;
    for (int t = 0; t < ntiles; t++) {
        if (t + 1 < ntiles) {
            const uint32_t sb = uS + ((t + 1) & 1) * 32768;
            const long j1 = (long)(t + 1) * 64;
#pragma unroll
            for (int i = 0; i < 2; i++) {
                long go = (j1 + kgo_row[i]) * kvstr + kch[i] * 16;
                cp_async16(sb + kso[i], gkh + go);
                cp_async16(sb + 8192 + kso[i], gkl + go);
                cp_async16(sb + 16384 + kso[i], gvh + go);
                cp_async16(sb + 24576 + kso[i], gvl + go);
            }
            CP_COMMIT();
            CP_WAIT(1);
        } else {
            CP_WAIT(0);
        }
        __syncthreads();

        const uint32_t sB = uS + (t & 1) * 32768;

        float sc[8][4];
#pragma unroll
        for (int j = 0; j < 8; j++)
#pragma unroll
            for (int v = 0; v < 4; v++) sc[j][v] = 0.f;

#pragma unroll
        for (int ks = 0; ks < 4; ks++) {
            uint32_t bh[8][2], bl[8][2];
            const int brow = lid & 15;
            const int bch = 2 * ks + (lid >> 4);
#pragma unroll
            for (int g = 0; g < 4; g++) {
                int r = g * 16 + brow;
                uint32_t off = sw_off8(r, bch);
                uint32_t t0, t1, t2, t3;
                ldsm_x4(sB + off, t0, t1, t2, t3);
                bh[2 * g][0] = t0; bh[2 * g][1] = t2;
                bh[2 * g + 1][0] = t1; bh[2 * g + 1][1] = t3;
                ldsm_x4(sB + 8192 + off, t0, t1, t2, t3);
                bl[2 * g][0] = t0; bl[2 * g][1] = t2;
                bl[2 * g + 1][0] = t1; bl[2 * g + 1][1] = t3;
            }
#pragma unroll
            for (int nj = 0; nj < 8; nj++)
                mma_bf16(sc[nj], qhf[ks], bh[nj]);
#pragma unroll
            for (int nj = 0; nj < 8; nj++)
                mma_bf16(sc[nj], qhf[ks], bl[nj]);
#pragma unroll
            for (int nj = 0; nj < 8; nj++)
                mma_bf16(sc[nj], qlf[ks], bh[nj]);
        }

        float mx0 = -INFINITY, mx1 = -INFINITY;
#pragma unroll
        for (int nj = 0; nj < 8; nj++) {
            sc[nj][0] *= scale; sc[nj][1] *= scale;
            sc[nj][2] *= scale; sc[nj][3] *= scale;
            mx0 = fmaxf(mx0, fmaxf(sc[nj][0], sc[nj][1]));
            mx1 = fmaxf(mx1, fmaxf(sc[nj][2], sc[nj][3]));
        }
        mx0 = fmaxf(mx0, __shfl_xor_sync(0xffffffffu, mx0, 1));
        mx0 = fmaxf(mx0, __shfl_xor_sync(0xffffffffu, mx0, 2));
        mx1 = fmaxf(mx1, __shfl_xor_sync(0xffffffffu, mx1, 1));
        mx1 = fmaxf(mx1, __shfl_xor_sync(0xffffffffu, mx1, 2));

        float mn0 = fmaxf(m0, mx0), mn1 = fmaxf(m1, mx1);
        float cor0 = __expf(m0 - mn0), cor1 = __expf(m1 - mn1);
        m0 = mn0; m1 = mn1;

        float sum0 = 0.f, sum1 = 0.f;
        uint32_t pah[4][4], pal[4][4];
#pragma unroll
        for (int nj = 0; nj < 8; nj++) {
            float p00 = __expf(sc[nj][0] - mn0);
            float p01 = __expf(sc[nj][1] - mn0);
            float p10 = __expf(sc[nj][2] - mn1);
            float p11 = __expf(sc[nj][3] - mn1);
            sum0 += p00 + p01;
            sum1 += p10 + p11;
            __nv_bfloat16 h00 = __float2bfloat16(p00), h01 = __float2bfloat16(p01);
            __nv_bfloat16 h10 = __float2bfloat16(p10), h11 = __float2bfloat16(p11);
            int ks = nj >> 1, half = nj & 1;
            pah[ks][half * 2]     = pack_bf16(__bfloat162float(h00), __bfloat162float(h01));
            pah[ks][half * 2 + 1] = pack_bf16(__bfloat162float(h10), __bfloat162float(h11));
            pal[ks][half * 2]     = pack_bf16(p00 - __bfloat162float(h00),
                                              p01 - __bfloat162float(h01));
            pal[ks][half * 2 + 1] = pack_bf16(p10 - __bfloat162float(h10),
                                              p11 - __bfloat162float(h11));
        }
        sum0 += __shfl_xor_sync(0xffffffffu, sum0, 1);
        sum0 += __shfl_xor_sync(0xffffffffu, sum0, 2);
        sum1 += __shfl_xor_sync(0xffffffffu, sum1, 1);
        sum1 += __shfl_xor_sync(0xffffffffu, sum1, 2);
        l0 = l0 * cor0 + sum0;
        l1 = l1 * cor1 + sum1;

#pragma unroll
        for (int nj = 0; nj < 8; nj++) {
            o[nj][0] *= cor0; o[nj][1] *= cor0;
            o[nj][2] *= cor1; o[nj][3] *= cor1;
        }

#pragma unroll
        for (int ks = 0; ks < 4; ks++) {
            uint32_t vh[8][2], vl[8][2];
            const int krow = ks * 16 + (lid & 15);
#pragma unroll
            for (int g = 0; g < 4; g++) {
                int ch = 2 * g + (lid >> 4);
                uint32_t off = sw_off8(krow, ch);
                uint32_t t0, t1, t2, t3;
                ldsm_x4_t(sB + 16384 + off, t0, t1, t2, t3);
                vh[2 * g][0] = t0; vh[2 * g][1] = t1;
                vh[2 * g + 1][0] = t2; vh[2 * g + 1][1] = t3;
                ldsm_x4_t(sB + 24576 + off, t0, t1, t2, t3);
                vl[2 * g][0] = t0; vl[2 * g][1] = t1;
                vl[2 * g + 1][0] = t2; vl[2 * g + 1][1] = t3;
            }
#pragma unroll
            for (int nj = 0; nj < 8; nj++)
                mma_bf16(o[nj], pah[ks], vh[nj]);
#pragma unroll
            for (int nj = 0; nj < 8; nj++)
                mma_bf16(o[nj], pah[ks], vl[nj]);
#pragma unroll
            for (int nj = 0; nj < 8; nj++)
                mma_bf16(o[nj], pal[ks], vh[nj]);
        }
        __syncthreads();
    }

    float inv0 = 1.f / l0, inv1 = 1.f / l1;
    int row0 = s0 + wid * 16 + (lid >> 2);
#pragma unroll
    for (int nj = 0; nj < 8; nj++) {
        int col = nj * 8 + (lid & 3) * 2;
        float v00 = o[nj][0] * inv0, v01 = o[nj][1] * inv0;
        float v10 = o[nj][2] * inv1, v11 = o[nj][3] * inv1;
        long a0 = (((long)(b * SS + row0)) * NH + h) * HD + col;
        long a1 = (((long)(b * SS + row0 + 8)) * NH + h) * HD + col;
        __nv_bfloat16 h00 = __float2bfloat16(v00), h01 = __float2bfloat16(v01);
        __nv_bfloat16 h10 = __float2bfloat16(v10), h11 = __float2bfloat16(v11);
        *(uint32_t*)(Oh + a0) = pack_bf16(__bfloat162float(h00), __bfloat162float(h01));
        *(uint32_t*)(Oh + a1) = pack_bf16(__bfloat162float(h10), __bfloat162float(h11));
        *(uint32_t*)(Ol + a0) = pack_bf16(v00 - __bfloat162float(h00),
                                          v01 - __bfloat162float(h01));
        *(uint32_t*)(Ol + a1) = pack_bf16(v10 - __bfloat162float(h10),
                                          v11 - __bfloat162float(h11));
    }
}

// ---------------------------------------------------------------------------
// Launch
// ---------------------------------------------------------------------------
#define GEMM_SMEM 131072
#define ATT_SMEM  65536

extern "C" void kernel_launch(void* const* d_in, const int* in_sizes, int n_in,
                              void* d_out, int out_size) {
    const float* x    = (const float*)d_in[0];
    const float* cosb = (const float*)d_in[1];
    const float* sinb = (const float*)d_in[2];
    const float* wq   = (const float*)d_in[3];
    const float* wk   = (const float*)d_in[4];
    const float* wv   = (const float*)d_in[5];
    const float* wo   = (const float*)d_in[6];
    float* out = (float*)d_out;

    // Idempotent, deterministic, capture-safe
    cudaFuncSetAttribute(gemm_qkv, cudaFuncAttributeMaxDynamicSharedMemorySize, GEMM_SMEM);
    cudaFuncSetAttribute(gemm_tc, cudaFuncAttributeMaxDynamicSharedMemorySize, GEMM_SMEM);
    cudaFuncSetAttribute(flash_attn_tc, cudaFuncAttributeMaxDynamicSharedMemorySize, ATT_SMEM);

    void *pq, *pk, *pv;
    cudaGetSymbolAddress(&pq, g_q);
    cudaGetSymbolAddress(&pk, g_k);
    cudaGetSymbolAddress(&pv, g_v);
    float* Q = (float*)pq;
    float* K = (float*)pk;
    float* V = (float*)pv;

    void *pxh, *pxl, *pqh2, *pql2, *pkh2, *pkl2, *pvh2, *pvl2, *poh, *pol, *pah, *pal;
    cudaGetSymbolAddress(&pxh, g_x_hi);  cudaGetSymbolAddress(&pxl, g_x_lo);
    cudaGetSymbolAddress(&pqh2, g_wq_hi); cudaGetSymbolAddress(&pql2, g_wq_lo);
    cudaGetSymbolAddress(&pkh2, g_wk_hi); cudaGetSymbolAddress(&pkl2, g_wk_lo);
    cudaGetSymbolAddress(&pvh2, g_wv_hi); cudaGetSymbolAddress(&pvl2, g_wv_lo);
    cudaGetSymbolAddress(&poh, g_wo_hi); cudaGetSymbolAddress(&pol, g_wo_lo);
    cudaGetSymbolAddress(&pah, g_a_hi);  cudaGetSymbolAddress(&pal, g_a_lo);

    void *qh, *ql, *kh, *kl, *vh, *vl;
    cudaGetSymbolAddress(&qh, g_qh); cudaGetSymbolAddress(&ql, g_ql);
    cudaGetSymbolAddress(&kh, g_kh); cudaGetSymbolAddress(&kl, g_kl);
    cudaGetSymbolAddress(&vh, g_vh); cudaGetSymbolAddress(&vl, g_vl);

    const int M = BB * SS;   // 4096
    const int HK = HIDD;     // 2048

    const int nx  = M * HIDD;
    const int nwq = NH * HD * HIDD;
    const int nwk = NKV * HD * HIDD;
    cvt_split<<<nx / 1024, 256>>>(x, (__nv_bfloat16*)pxh, (__nv_bfloat16*)pxl, nx);
    cvt_split<<<nwq / 1024, 256>>>(wq, (__nv_bfloat16*)pqh2, (__nv_bfloat16*)pql2, nwq);
    cvt_split<<<nwk / 1024, 256>>>(wk, (__nv_bfloat16*)pkh2, (__nv_bfloat16*)pkl2, nwk);
    cvt_split<<<nwk / 1024, 256>>>(wv, (__nv_bfloat16*)pvh2, (__nv_bfloat16*)pvl2, nwk);
    cvt_split<<<nwq / 1024, 256>>>(wo, (__nv_bfloat16*)poh, (__nv_bfloat16*)pol, nwq);

    // Fused Q/K/V projections
    gemm_qkv<<<dim3(24, M / 128), 512, GEMM_SMEM>>>(
        (const __nv_bfloat16*)pxh, (const __nv_bfloat16*)pxl,
        (const __nv_bfloat16*)pqh2, (const __nv_bfloat16*)pql2,
        (const __nv_bfloat16*)pkh2, (const __nv_bfloat16*)pkl2,
        (const __nv_bfloat16*)pvh2, (const __nv_bfloat16*)pvl2,
        Q, K, V);

    // RoPE + split (Q, K); plain split (V)
    int qpairs = BB * SS * NH * 32;
    int kpairs = BB * SS * NKV * 32;
    rope_split<<<(qpairs + 255) / 256, 256>>>(Q, cosb, sinb,
        (__nv_bfloat16*)qh, (__nv_bfloat16*)ql, NH, qpairs);
    rope_split<<<(kpairs + 255) / 256, 256>>>(K, cosb, sinb,
        (__nv_bfloat16*)kh, (__nv_bfloat16*)kl, NKV, kpairs);
    const int nv = BB * SS * NKV * HD;
    cvt_split<<<nv / 1024, 256>>>(V, (__nv_bfloat16*)vh, (__nv_bfloat16*)vl, nv);

    // Attention
    flash_attn_tc<<<dim3(SS / 128, NH, BB), 256, ATT_SMEM>>>(
        (const __nv_bfloat16*)qh, (const __nv_bfloat16*)ql,
        (const __nv_bfloat16*)kh, (const __nv_bfloat16*)kl,
        (const __nv_bfloat16*)vh, (const __nv_bfloat16*)vl,
        (__nv_bfloat16*)pah, (__nv_bfloat16*)pal);

    // Output projection
    gemm_tc<<<dim3(HIDD / 128, M / 128), 512, GEMM_SMEM>>>(
        (const __nv_bfloat16*)pah, (const __nv_bfloat16*)pal,
        (const __nv_bfloat16*)poh, (const __nv_bfloat16*)pol, out, M, HIDD, HK);
}